// round 4
// baseline (speedup 1.0000x reference)
#include <cuda_runtime.h>
#include <cuda_bf16.h>

// Problem constants
#define BATCH 4
#define CIN   64
#define HH    128
#define WW    128
#define OUTC  64
#define K2N   9
#define NPOS  (BATCH*HH*WW)

// Scratch (device globals; no allocation allowed)
__device__ float g_xT[BATCH*HH*WW*CIN];        // [b][y][x][c]   16 MB
__device__ float g_post[NPOS*28];              // per position: [0..17]=offset(dy,dx per k), [18..26]=sigmoid mask, [27]=pad
__device__ float g_cwT[9*64*28];               // [tap][c][j]  combined offset(18)+mask(9)+pad
__device__ float g_dwT[9*64*64];               // [k][c][o]

// ---------------------------------------------------------------------------
// Kernel W: weight transposes (tiny)
// ---------------------------------------------------------------------------
__global__ void kW(const float* __restrict__ ow, const float* __restrict__ mw,
                   const float* __restrict__ dw) {
    int i = blockIdx.x * blockDim.x + threadIdx.x;
    int stride = gridDim.x * blockDim.x;
    for (int idx = i; idx < 9*64*28; idx += stride) {
        int j   = idx % 28;
        int c   = (idx / 28) % 64;
        int tap = idx / (28*64);
        float v = 0.f;
        if (j < 18)      v = ow[j*576 + c*9 + tap];          // offset_w[j][c][ky][kx]
        else if (j < 27) v = mw[(j-18)*576 + c*9 + tap];     // mask_w
        g_cwT[idx] = v;
    }
    for (int idx = i; idx < 9*64*64; idx += stride) {
        int o = idx % 64;
        int c = (idx / 64) % 64;
        int k = idx / 4096;
        g_dwT[idx] = dw[o*576 + c*9 + k];                    // deform_w[o][c][k]
    }
}

// ---------------------------------------------------------------------------
// Kernel A: NCHW -> NHWC transpose of x
// grid = BATCH*HH, block = 128 (one thread per x)
// ---------------------------------------------------------------------------
__global__ __launch_bounds__(128) void kA(const float* __restrict__ x) {
    int by = blockIdx.x;
    int b = by >> 7, y = by & 127;
    int xq = threadIdx.x;
    const float* src = x + ((size_t)(b*CIN)*HH + y) * WW + xq;  // channel 0 at this (b,y,x)
    float* dst = g_xT + (((size_t)b*HH + y) * WW + xq) * CIN;
#pragma unroll
    for (int c4 = 0; c4 < 16; ++c4) {
        float4 v;
        v.x = src[(size_t)(c4*4+0)*HH*WW];
        v.y = src[(size_t)(c4*4+1)*HH*WW];
        v.z = src[(size_t)(c4*4+2)*HH*WW];
        v.w = src[(size_t)(c4*4+3)*HH*WW];
        *reinterpret_cast<float4*>(dst + c4*4) = v;
    }
}

// ---------------------------------------------------------------------------
// Kernel B: offset + mask conv (3x3, Cin=64, Cout=27), fused sigmoid on mask
// grid = BATCH*HH, block = 128. Thread-per-position, 28 reg accumulators.
// ---------------------------------------------------------------------------
__global__ __launch_bounds__(128) void kB(const float* __restrict__ ob,
                                          const float* __restrict__ mb) {
    __shared__ float sw[64*28];   // weights for one tap: [c][j]
    int by = blockIdx.x;
    int b = by >> 7, y = by & 127;
    int xq = threadIdx.x;

    float acc[28];
#pragma unroll
    for (int j = 0; j < 28; ++j) acc[j] = 0.f;

    for (int tap = 0; tap < 9; ++tap) {
        __syncthreads();
        for (int t = threadIdx.x; t < 64*28/4; t += 128)
            reinterpret_cast<float4*>(sw)[t] =
                reinterpret_cast<const float4*>(g_cwT + tap*64*28)[t];
        __syncthreads();

        int ky = tap / 3, kx = tap % 3;
        int ys = y + ky - 1, xs = xq + kx - 1;
        if (ys < 0 || ys > 127 || xs < 0 || xs > 127) continue;  // zero pad

        const float4* xp = reinterpret_cast<const float4*>(
            g_xT + (((size_t)b*HH + ys) * WW + xs) * CIN);
#pragma unroll 4
        for (int c4 = 0; c4 < 16; ++c4) {
            float4 xv = xp[c4];
#pragma unroll
            for (int cc = 0; cc < 4; ++cc) {
                float v = (&xv.x)[cc];
                const float4* wp = reinterpret_cast<const float4*>(sw + (c4*4+cc)*28);
#pragma unroll
                for (int j4 = 0; j4 < 7; ++j4) {
                    float4 w = wp[j4];
                    acc[j4*4+0] += v * w.x;
                    acc[j4*4+1] += v * w.y;
                    acc[j4*4+2] += v * w.z;
                    acc[j4*4+3] += v * w.w;
                }
            }
        }
    }

    float* dst = g_post + (((size_t)(b*HH) + y) * WW + xq) * 28;
#pragma unroll
    for (int j = 0; j < 18; ++j) dst[j] = acc[j] + ob[j];
#pragma unroll
    for (int j = 0; j < 9; ++j) {
        float t = acc[18+j] + mb[j];
        dst[18+j] = 1.f / (1.f + __expf(-t));
    }
    dst[27] = 0.f;
}

// ---------------------------------------------------------------------------
// Kernel C: bilinear sampling + deform GEMM
// grid = BATCH*HH, block = 128. Thread-per-position, 64 reg accumulators.
// ---------------------------------------------------------------------------
__global__ __launch_bounds__(128) void kC(const float* __restrict__ db,
                                          float* __restrict__ out) {
    __shared__ float sw[64*64];   // dw slab for one k: [c][o]
    int by = blockIdx.x;
    int b = by >> 7, y = by & 127;
    int xq = threadIdx.x;

    float acc[64];
#pragma unroll
    for (int o = 0; o < 64; ++o) acc[o] = db[o];

    const float* pi = g_post + (((size_t)(b*HH) + y) * WW + xq) * 28;

    for (int k = 0; k < 9; ++k) {
        __syncthreads();
        for (int t = threadIdx.x; t < 1024; t += 128)
            reinterpret_cast<float4*>(sw)[t] =
                reinterpret_cast<const float4*>(g_dwT + k*4096)[t];
        __syncthreads();

        float dy = pi[2*k], dx = pi[2*k+1], m = pi[18+k];
        int ky = k / 3, kx = k % 3;
        float py = dy + (float)(ky + y - 1);
        float px = dx + (float)(kx + xq - 1);
        float fy = floorf(py), fx = floorf(px);
        float wy1 = py - fy, wx1 = px - fx;
        float wy0 = 1.f - wy1, wx0 = 1.f - wx1;
        int y0 = (int)fy, x0 = (int)fx;
        int y1 = y0 + 1, x1 = x0 + 1;
        bool vy0 = (y0 >= 0) & (y0 < HH), vy1 = (y1 >= 0) & (y1 < HH);
        bool vx0 = (x0 >= 0) & (x0 < WW), vx1 = (x1 >= 0) & (x1 < WW);
        float w00 = (vy0 && vx0) ? wy0*wx0*m : 0.f;
        float w01 = (vy0 && vx1) ? wy0*wx1*m : 0.f;
        float w10 = (vy1 && vx0) ? wy1*wx0*m : 0.f;
        float w11 = (vy1 && vx1) ? wy1*wx1*m : 0.f;
        int yc0 = min(max(y0, 0), HH-1), yc1 = min(max(y1, 0), HH-1);
        int xc0 = min(max(x0, 0), WW-1), xc1 = min(max(x1, 0), WW-1);

        const float4* p00 = reinterpret_cast<const float4*>(g_xT + (((size_t)b*HH + yc0)*WW + xc0)*CIN);
        const float4* p01 = reinterpret_cast<const float4*>(g_xT + (((size_t)b*HH + yc0)*WW + xc1)*CIN);
        const float4* p10 = reinterpret_cast<const float4*>(g_xT + (((size_t)b*HH + yc1)*WW + xc0)*CIN);
        const float4* p11 = reinterpret_cast<const float4*>(g_xT + (((size_t)b*HH + yc1)*WW + xc1)*CIN);

#pragma unroll 4
        for (int c4 = 0; c4 < 16; ++c4) {
            float4 a = p00[c4], bb = p01[c4], cv = p10[c4], d = p11[c4];
            float4 v;
            v.x = w00*a.x + w01*bb.x + w10*cv.x + w11*d.x;
            v.y = w00*a.y + w01*bb.y + w10*cv.y + w11*d.y;
            v.z = w00*a.z + w01*bb.z + w10*cv.z + w11*d.z;
            v.w = w00*a.w + w01*bb.w + w10*cv.w + w11*d.w;
#pragma unroll
            for (int cc = 0; cc < 4; ++cc) {
                float vv = (&v.x)[cc];
                const float4* wp = reinterpret_cast<const float4*>(sw + (c4*4+cc)*64);
#pragma unroll
                for (int o4 = 0; o4 < 16; ++o4) {
                    float4 w = wp[o4];
                    acc[o4*4+0] += vv * w.x;
                    acc[o4*4+1] += vv * w.y;
                    acc[o4*4+2] += vv * w.z;
                    acc[o4*4+3] += vv * w.w;
                }
            }
        }
    }

    float* op = out + (((size_t)b*OUTC)*HH + y) * WW + xq;
#pragma unroll
    for (int o = 0; o < 64; ++o) op[(size_t)o*HH*WW] = acc[o];
}

// ---------------------------------------------------------------------------
extern "C" void kernel_launch(void* const* d_in, const int* in_sizes, int n_in,
                              void* d_out, int out_size) {
    const float* x   = (const float*)d_in[0];
    const float* ow  = (const float*)d_in[1];
    const float* ob  = (const float*)d_in[2];
    const float* mw  = (const float*)d_in[3];
    const float* mb  = (const float*)d_in[4];
    const float* dw  = (const float*)d_in[5];
    const float* db  = (const float*)d_in[6];
    float* out = (float*)d_out;

    kW<<<64, 256>>>(ow, mw, dw);
    kA<<<BATCH*HH, 128>>>(x);
    kB<<<BATCH*HH, 128>>>(ob, mb);
    kC<<<BATCH*HH, 128>>>(db, out);
}

// round 5
// speedup vs baseline: 1.2581x; 1.2581x over previous
#include <cuda_runtime.h>
#include <cuda_bf16.h>

// Problem constants
#define BATCH 4
#define CIN   64
#define HH    128
#define WW    128
#define OUTC  64
#define K2N   9
#define NPOS  (BATCH*HH*WW)

// Scratch (device globals; no allocation allowed)
__device__ __align__(16) float g_xT[BATCH*HH*WW*CIN];   // [b][y][x][c]
__device__ __align__(16) float g_post[NPOS*28];         // [0..17]=offsets, [18..26]=sigmoid mask, [27]=pad
__device__ __align__(16) float g_cwT[9*64*28];          // [tap][c][j]
__device__ __align__(16) float g_dwD[9*2*64*64];        // [k][h][c][2*ol+dup] : deform weights duplicated in pairs

// ------------------------- f32x2 helpers (sm_100+) -------------------------
__device__ __forceinline__ void ffma2(unsigned long long& d,
                                      unsigned long long a,
                                      unsigned long long b) {
    asm("fma.rn.f32x2 %0, %1, %2, %0;" : "+l"(d) : "l"(a), "l"(b));
}
__device__ __forceinline__ unsigned long long dup2(float a) {
    unsigned long long r;
    asm("mov.b64 %0, {%1, %1};" : "=l"(r) : "f"(a));
    return r;
}

// ---------------------------------------------------------------------------
// Kernel W: weight transposes (tiny)
// ---------------------------------------------------------------------------
__global__ void kW(const float* __restrict__ ow, const float* __restrict__ mw,
                   const float* __restrict__ dw) {
    int i = blockIdx.x * blockDim.x + threadIdx.x;
    int stride = gridDim.x * blockDim.x;
    for (int idx = i; idx < 9*64*28; idx += stride) {
        int j   = idx % 28;
        int c   = (idx / 28) % 64;
        int tap = idx / (28*64);
        float v = 0.f;
        if (j < 18)      v = ow[j*576 + c*9 + tap];
        else if (j < 27) v = mw[(j-18)*576 + c*9 + tap];
        g_cwT[idx] = v;
    }
    // duplicated deform weights: g_dwD[k][h][c][2*ol + d] = dw[h*32+ol][c][k]
    for (int idx = i; idx < 9*2*64*64; idx += stride) {
        int ol = (idx & 63) >> 1;
        int c  = (idx >> 6) & 63;
        int h  = (idx >> 12) & 1;
        int k  = idx >> 13;
        int o  = h*32 + ol;
        g_dwD[idx] = dw[o*576 + c*9 + k];
    }
}

// ---------------------------------------------------------------------------
// Kernel A: NCHW -> NHWC transpose of x  (grid = BATCH*HH, block = 128)
// ---------------------------------------------------------------------------
__global__ __launch_bounds__(128) void kA(const float* __restrict__ x) {
    int by = blockIdx.x;
    int b = by >> 7, y = by & 127;
    int xq = threadIdx.x;
    const float* src = x + ((size_t)(b*CIN)*HH + y) * WW + xq;
    float* dst = g_xT + (((size_t)b*HH + y) * WW + xq) * CIN;
#pragma unroll
    for (int c4 = 0; c4 < 16; ++c4) {
        float4 v;
        v.x = src[(size_t)(c4*4+0)*HH*WW];
        v.y = src[(size_t)(c4*4+1)*HH*WW];
        v.z = src[(size_t)(c4*4+2)*HH*WW];
        v.w = src[(size_t)(c4*4+3)*HH*WW];
        *reinterpret_cast<float4*>(dst + c4*4) = v;
    }
}

// ---------------------------------------------------------------------------
// Kernel B: offset + mask conv (3x3, Cin=64, Cout=27), fused sigmoid.
// j-pair packed FFMA2: acc = 14 f32x2 pairs. grid = BATCH*HH, block = 128.
// ---------------------------------------------------------------------------
__global__ __launch_bounds__(128) void kB(const float* __restrict__ ob,
                                          const float* __restrict__ mb) {
    __shared__ __align__(16) float sw[64*28];   // weights for one tap: [c][28]
    int by = blockIdx.x;
    int b = by >> 7, y = by & 127;
    int xq = threadIdx.x;

    unsigned long long acc[14];
#pragma unroll
    for (int j = 0; j < 14; ++j) acc[j] = 0ULL;

    for (int tap = 0; tap < 9; ++tap) {
        __syncthreads();
        for (int t = threadIdx.x; t < 64*28/4; t += 128)
            reinterpret_cast<float4*>(sw)[t] =
                reinterpret_cast<const float4*>(g_cwT + tap*64*28)[t];
        __syncthreads();

        int ky = tap / 3, kx = tap % 3;
        int ys = y + ky - 1, xs = xq + kx - 1;
        if (ys < 0 || ys > 127 || xs < 0 || xs > 127) continue;  // zero pad

        const float4* xp = reinterpret_cast<const float4*>(
            g_xT + (((size_t)b*HH + ys) * WW + xs) * CIN);
#pragma unroll 4
        for (int c4 = 0; c4 < 16; ++c4) {
            float4 xv = xp[c4];
#pragma unroll
            for (int cc = 0; cc < 4; ++cc) {
                unsigned long long ad = dup2((&xv.x)[cc]);
                const float4* wp = reinterpret_cast<const float4*>(sw + (c4*4+cc)*28);
#pragma unroll
                for (int j4 = 0; j4 < 7; ++j4) {
                    float4 w = wp[j4];
                    const unsigned long long* wu =
                        reinterpret_cast<const unsigned long long*>(&w);
                    ffma2(acc[j4*2+0], ad, wu[0]);
                    ffma2(acc[j4*2+1], ad, wu[1]);
                }
            }
        }
    }

    float res[28];
#pragma unroll
    for (int j2 = 0; j2 < 14; ++j2) {
        float2 f = *reinterpret_cast<float2*>(&acc[j2]);
        res[2*j2+0] = f.x;
        res[2*j2+1] = f.y;
    }
    float* dst = g_post + (((size_t)(b*HH) + y) * WW + xq) * 28;
#pragma unroll
    for (int j = 0; j < 18; ++j) dst[j] = res[j] + ob[j];
#pragma unroll
    for (int j = 0; j < 9; ++j) {
        float t = res[18+j] + mb[j];
        dst[18+j] = 1.f / (1.f + __expf(-t));
    }
    dst[27] = 0.f;
}

// ---------------------------------------------------------------------------
// Kernel C: bilinear sampling + deform GEMM, FFMA2 register-blocked.
// grid = BATCH*HH (one (b,y) row per block), block = 128.
// Smem: A tile [64c][128pos] (32KB) + dup'd W slab [64c][64] (16KB) = 48KB.
// Thread tile: 8 positions (4 strided pairs) x 8 outputs (2 halves x 4).
// ---------------------------------------------------------------------------
__global__ __launch_bounds__(128) void kC(const float* __restrict__ db,
                                          float* __restrict__ out) {
    __shared__ __align__(16) float A_sh[64][128];
    __shared__ __align__(16) float Wd_sh[64][64];

    int by = blockIdx.x;
    int b = by >> 7, y = by & 127;
    int tid  = threadIdx.x;
    int pcol = tid & 15;     // position-pair column: x pairs at pcol*2 + i2*32
    int og   = tid >> 4;     // output group 0..7: o = h*32 + og*4 + j

    // accumulators: acc[h][i2*4 + j] = f32x2 pair over two adjacent x
    unsigned long long acc[2][16];
#pragma unroll
    for (int h = 0; h < 2; ++h)
#pragma unroll
        for (int j = 0; j < 4; ++j) {
            unsigned long long bd = dup2(db[h*32 + og*4 + j]);
#pragma unroll
            for (int i2 = 0; i2 < 4; ++i2) acc[h][i2*4+j] = bd;
        }

    const float* pi = g_post + (((size_t)(b*HH) + y) * WW + tid) * 28;

    for (int k = 0; k < 9; ++k) {
        __syncthreads();  // protect A_sh / Wd_sh from previous iteration readers

        // ---- sampling: thread = position tid, write A_sh[c][tid] ----
        {
            float dy = pi[2*k], dx = pi[2*k+1], m = pi[18+k];
            int ky = k / 3, kx = k % 3;
            float py = dy + (float)(ky + y   - 1);
            float px = dx + (float)(kx + tid - 1);
            float fy = floorf(py), fx = floorf(px);
            float wy1 = py - fy, wx1 = px - fx;
            float wy0 = 1.f - wy1, wx0 = 1.f - wx1;
            int y0 = (int)fy, x0 = (int)fx;
            int y1 = y0 + 1, x1 = x0 + 1;
            bool vy0 = (y0 >= 0) & (y0 < HH), vy1 = (y1 >= 0) & (y1 < HH);
            bool vx0 = (x0 >= 0) & (x0 < WW), vx1 = (x1 >= 0) & (x1 < WW);
            float w00 = (vy0 && vx0) ? wy0*wx0*m : 0.f;
            float w01 = (vy0 && vx1) ? wy0*wx1*m : 0.f;
            float w10 = (vy1 && vx0) ? wy1*wx0*m : 0.f;
            float w11 = (vy1 && vx1) ? wy1*wx1*m : 0.f;
            int yc0 = min(max(y0, 0), HH-1), yc1 = min(max(y1, 0), HH-1);
            int xc0 = min(max(x0, 0), WW-1), xc1 = min(max(x1, 0), WW-1);

            const float4* p00 = reinterpret_cast<const float4*>(g_xT + (((size_t)b*HH + yc0)*WW + xc0)*CIN);
            const float4* p01 = reinterpret_cast<const float4*>(g_xT + (((size_t)b*HH + yc0)*WW + xc1)*CIN);
            const float4* p10 = reinterpret_cast<const float4*>(g_xT + (((size_t)b*HH + yc1)*WW + xc0)*CIN);
            const float4* p11 = reinterpret_cast<const float4*>(g_xT + (((size_t)b*HH + yc1)*WW + xc1)*CIN);

#pragma unroll 4
            for (int c4 = 0; c4 < 16; ++c4) {
                float4 a = p00[c4], bb = p01[c4], cv = p10[c4], d = p11[c4];
                float vx_, vy_, vz_, vw_;
                vx_ = w00*a.x + w01*bb.x + w10*cv.x + w11*d.x;
                vy_ = w00*a.y + w01*bb.y + w10*cv.y + w11*d.y;
                vz_ = w00*a.z + w01*bb.z + w10*cv.z + w11*d.z;
                vw_ = w00*a.w + w01*bb.w + w10*cv.w + w11*d.w;
                A_sh[c4*4+0][tid] = vx_;
                A_sh[c4*4+1][tid] = vy_;
                A_sh[c4*4+2][tid] = vz_;
                A_sh[c4*4+3][tid] = vw_;
            }
        }

        // ---- GEMM over two output halves ----
#pragma unroll
        for (int h = 0; h < 2; ++h) {
            __syncthreads();  // h=0: A ready; h=1: previous half done reading Wd
            {
                const float4* src = reinterpret_cast<const float4*>(
                    g_dwD + ((size_t)(k*2 + h)) * 4096);
                for (int t = tid; t < 1024; t += 128)
                    reinterpret_cast<float4*>(&Wd_sh[0][0])[t] = src[t];
            }
            __syncthreads();  // Wd ready (and A visible)

#pragma unroll 8
            for (int c = 0; c < 64; ++c) {
                const unsigned long long* wp =
                    reinterpret_cast<const unsigned long long*>(&Wd_sh[c][og*8]);
                unsigned long long w0 = wp[0], w1 = wp[1], w2 = wp[2], w3 = wp[3];
                const float* ac = &A_sh[c][pcol*2];
                unsigned long long a0 = *reinterpret_cast<const unsigned long long*>(ac);
                unsigned long long a1 = *reinterpret_cast<const unsigned long long*>(ac + 32);
                unsigned long long a2 = *reinterpret_cast<const unsigned long long*>(ac + 64);
                unsigned long long a3 = *reinterpret_cast<const unsigned long long*>(ac + 96);

                ffma2(acc[h][ 0], a0, w0); ffma2(acc[h][ 1], a0, w1);
                ffma2(acc[h][ 2], a0, w2); ffma2(acc[h][ 3], a0, w3);
                ffma2(acc[h][ 4], a1, w0); ffma2(acc[h][ 5], a1, w1);
                ffma2(acc[h][ 6], a1, w2); ffma2(acc[h][ 7], a1, w3);
                ffma2(acc[h][ 8], a2, w0); ffma2(acc[h][ 9], a2, w1);
                ffma2(acc[h][10], a2, w2); ffma2(acc[h][11], a2, w3);
                ffma2(acc[h][12], a3, w0); ffma2(acc[h][13], a3, w1);
                ffma2(acc[h][14], a3, w2); ffma2(acc[h][15], a3, w3);
            }
        }
    }

    // ---- epilogue: packed 8-byte stores, coalesced per half-warp ----
#pragma unroll
    for (int h = 0; h < 2; ++h)
#pragma unroll
        for (int j = 0; j < 4; ++j) {
            int o = h*32 + og*4 + j;
            float* orow = out + (((size_t)(b*OUTC) + o)*HH + y) * WW;
#pragma unroll
            for (int i2 = 0; i2 < 4; ++i2)
                *reinterpret_cast<unsigned long long*>(orow + pcol*2 + i2*32) =
                    acc[h][i2*4+j];
        }
}

// ---------------------------------------------------------------------------
extern "C" void kernel_launch(void* const* d_in, const int* in_sizes, int n_in,
                              void* d_out, int out_size) {
    const float* x   = (const float*)d_in[0];
    const float* ow  = (const float*)d_in[1];
    const float* ob  = (const float*)d_in[2];
    const float* mw  = (const float*)d_in[3];
    const float* mb  = (const float*)d_in[4];
    const float* dw  = (const float*)d_in[5];
    const float* db  = (const float*)d_in[6];
    float* out = (float*)d_out;

    kW<<<64, 256>>>(ow, mw, dw);
    kA<<<BATCH*HH, 128>>>(x);
    kB<<<BATCH*HH, 128>>>(ob, mb);
    kC<<<BATCH*HH, 128>>>(db, out);
}